// round 12
// baseline (speedup 1.0000x reference)
#include <cuda_runtime.h>
#include <cstdint>

#define MAX_SEGS 65536
#define MAX_NB   64
#define SCAN_BLK 1024

__device__ int g_starts[MAX_SEGS];   // chunk-local exclusive prefix
__device__ int g_blocktot[MAX_NB];   // per-chunk totals

// ---------------------------------------------------------------------------
// K1: per-chunk exclusive scan. grid = ceil(n/1024), block = 1024.
// Deliberately dumb: no atomics, no fences — minimal tail before
// launch_dependents so the dependent grid releases ASAP (R7-proven).
// ---------------------------------------------------------------------------
__global__ void scan_local_kernel(const int* __restrict__ sz, int n) {
    __shared__ int s_tot[32];
    __shared__ int s_off[32];

    const int t    = threadIdx.x;
    const int lane = t & 31;
    const int wid  = t >> 5;
    const int gidx = blockIdx.x * SCAN_BLK + t;

    int v = (gidx < n) ? sz[gidx] : 0;

    int inc = v;
    #pragma unroll
    for (int d = 1; d < 32; d <<= 1) {
        int u = __shfl_up_sync(0xFFFFFFFFu, inc, d);
        if (lane >= d) inc += u;
    }
    if (lane == 31) s_tot[wid] = inc;
    __syncthreads();

    if (wid == 0) {
        int wv = s_tot[lane];
        int winc = wv;
        #pragma unroll
        for (int d = 1; d < 32; d <<= 1) {
            int u = __shfl_up_sync(0xFFFFFFFFu, winc, d);
            if (lane >= d) winc += u;
        }
        s_off[lane] = winc - wv;
        if (lane == 31) g_blocktot[blockIdx.x] = winc;
    }
    __syncthreads();

    if (gidx < n) g_starts[gidx] = s_off[wid] + (inc - v);

    asm volatile("griddepcontrol.launch_dependents;" ::: "memory");
}

// ---------------------------------------------------------------------------
// K2: one CTA per segment. Barrier-free prologue: every warp redundantly
// reduces the predecessor chunk totals (predicated loads + 5 shfl_xor) and
// adds the broadcast g_starts[seg] load. Then the proven MLP=8 body.
// ---------------------------------------------------------------------------
__global__ __launch_bounds__(128)
void seg_mean_kernel(const float* __restrict__ data,
                     const int* __restrict__ sz,
                     float* __restrict__ out) {
    const int seg = blockIdx.x;
    const int t = threadIdx.x;
    const int w = t >> 5;
    const int l = t & 31;

    const int len = sz[seg];            // independent of scan: issue early

    asm volatile("griddepcontrol.wait;" ::: "memory");

    // per-warp redundant reduce of blocktots for chunks < b  (b <= 63)
    const int b = seg >> 10;
    int s = ((l      < b) ? g_blocktot[l]      : 0)
          + ((l + 32 < b) ? g_blocktot[l + 32] : 0);
    #pragma unroll
    for (int d = 16; d > 0; d >>= 1)
        s += __shfl_xor_sync(0xFFFFFFFFu, s, d);
    const int start = s + g_starts[seg];   // broadcast load, same addr all lanes

    const float4* __restrict__ base =
        reinterpret_cast<const float4*>(data) + (size_t)start * 32 + l;

    float4 acc = make_float4(0.f, 0.f, 0.f, 0.f);

    if (len == 64) {
        #pragma unroll
        for (int bb = 0; bb < 2; ++bb) {
            float4 v[8];
            #pragma unroll
            for (int i = 0; i < 8; ++i)
                v[i] = __ldcs(&base[(size_t)(w + (bb * 8 + i) * 4) * 32]);
            #pragma unroll
            for (int i = 0; i < 8; ++i) {
                acc.x += v[i].x; acc.y += v[i].y;
                acc.z += v[i].z; acc.w += v[i].w;
            }
        }
    } else {
        int r = w;
        for (; r + 12 < len; r += 16) {
            float4 v0 = __ldcs(&base[(size_t)(r     ) * 32]);
            float4 v1 = __ldcs(&base[(size_t)(r +  4) * 32]);
            float4 v2 = __ldcs(&base[(size_t)(r +  8) * 32]);
            float4 v3 = __ldcs(&base[(size_t)(r + 12) * 32]);
            acc.x += v0.x + v1.x + v2.x + v3.x;
            acc.y += v0.y + v1.y + v2.y + v3.y;
            acc.z += v0.z + v1.z + v2.z + v3.z;
            acc.w += v0.w + v1.w + v2.w + v3.w;
        }
        for (; r < len; r += 4) {
            float4 v = __ldcs(&base[(size_t)r * 32]);
            acc.x += v.x; acc.y += v.y; acc.z += v.z; acc.w += v.w;
        }
    }

    __shared__ float4 sm[4][32];
    sm[w][l] = acc;
    __syncthreads();

    if (w == 0) {
        float4 a = sm[0][l];
        float4 bb = sm[1][l];
        float4 c = sm[2][l];
        float4 d = sm[3][l];
        const float inv = (len > 0) ? (1.0f / (float)len) : 0.0f;
        float4 o;
        o.x = (a.x + bb.x + c.x + d.x) * inv;
        o.y = (a.y + bb.y + c.y + d.y) * inv;
        o.z = (a.z + bb.z + c.z + d.z) * inv;
        o.w = (a.w + bb.w + c.w + d.w) * inv;
        __stcs(&reinterpret_cast<float4*>(out)[(size_t)seg * 32 + l], o);
    }
}

// ---------------------------------------------------------------------------
// kernel_launch: 2 nodes, PDL-chained (R7-proven structure).
// ---------------------------------------------------------------------------
extern "C" void kernel_launch(void* const* d_in, const int* in_sizes, int n_in,
                              void* d_out, int out_size) {
    const float* data = (const float*)d_in[0];
    const int*   sz   = (const int*)d_in[1];
    float*       out  = (float*)d_out;
    const int n_seg = in_sizes[1];
    const int nb    = (n_seg + SCAN_BLK - 1) / SCAN_BLK;

    scan_local_kernel<<<nb, SCAN_BLK>>>(sz, n_seg);

    cudaLaunchConfig_t cfg = {};
    cfg.gridDim  = dim3((unsigned)n_seg, 1, 1);
    cfg.blockDim = dim3(128, 1, 1);
    cfg.stream = 0;

    cudaLaunchAttribute attrs[1];
    attrs[0].id = cudaLaunchAttributeProgrammaticStreamSerialization;
    attrs[0].val.programmaticStreamSerializationAllowed = 1;
    cfg.attrs = attrs;
    cfg.numAttrs = 1;

    cudaLaunchKernelEx(&cfg, seg_mean_kernel, data, sz, out);
}

// round 13
// speedup vs baseline: 1.0038x; 1.0038x over previous
#include <cuda_runtime.h>
#include <cstdint>

#define MAX_SEGS 65536
#define MAX_NB   64
#define SCAN_BLK 1024

__device__ int g_starts[MAX_SEGS];   // chunk-local exclusive prefix
__device__ int g_blocktot[MAX_NB];   // per-chunk totals

// ---------------------------------------------------------------------------
// K1: per-chunk exclusive scan. grid = ceil(n/1024), block = 1024.
// Deliberately dumb: no atomics, no fences — minimal tail before
// launch_dependents so the dependent grid releases ASAP (R7-proven).
// ---------------------------------------------------------------------------
__global__ void scan_local_kernel(const int* __restrict__ sz, int n) {
    __shared__ int s_tot[32];
    __shared__ int s_off[32];

    const int t    = threadIdx.x;
    const int lane = t & 31;
    const int wid  = t >> 5;
    const int gidx = blockIdx.x * SCAN_BLK + t;

    int v = (gidx < n) ? sz[gidx] : 0;

    int inc = v;
    #pragma unroll
    for (int d = 1; d < 32; d <<= 1) {
        int u = __shfl_up_sync(0xFFFFFFFFu, inc, d);
        if (lane >= d) inc += u;
    }
    if (lane == 31) s_tot[wid] = inc;
    __syncthreads();

    if (wid == 0) {
        int wv = s_tot[lane];
        int winc = wv;
        #pragma unroll
        for (int d = 1; d < 32; d <<= 1) {
            int u = __shfl_up_sync(0xFFFFFFFFu, winc, d);
            if (lane >= d) winc += u;
        }
        s_off[lane] = winc - wv;
        if (lane == 31) g_blocktot[blockIdx.x] = winc;
    }
    __syncthreads();

    if (gidx < n) g_starts[gidx] = s_off[wid] + (inc - v);

    asm volatile("griddepcontrol.launch_dependents;" ::: "memory");
}

// ---------------------------------------------------------------------------
// K2: one CTA per segment. Barrier-free prologue: every warp redundantly
// reduces the predecessor chunk totals (predicated loads + 5 shfl_xor) and
// adds the broadcast g_starts[seg] load. Then the proven MLP=8 body.
// ---------------------------------------------------------------------------
__global__ __launch_bounds__(128)
void seg_mean_kernel(const float* __restrict__ data,
                     const int* __restrict__ sz,
                     float* __restrict__ out) {
    const int seg = blockIdx.x;
    const int t = threadIdx.x;
    const int w = t >> 5;
    const int l = t & 31;

    const int len = sz[seg];            // independent of scan: issue early

    asm volatile("griddepcontrol.wait;" ::: "memory");

    // per-warp redundant reduce of blocktots for chunks < b  (b <= 63)
    const int b = seg >> 10;
    int s = ((l      < b) ? g_blocktot[l]      : 0)
          + ((l + 32 < b) ? g_blocktot[l + 32] : 0);
    #pragma unroll
    for (int d = 16; d > 0; d >>= 1)
        s += __shfl_xor_sync(0xFFFFFFFFu, s, d);
    const int start = s + g_starts[seg];   // broadcast load, same addr all lanes

    const float4* __restrict__ base =
        reinterpret_cast<const float4*>(data) + (size_t)start * 32 + l;

    float4 acc = make_float4(0.f, 0.f, 0.f, 0.f);

    if (len == 64) {
        #pragma unroll
        for (int bb = 0; bb < 2; ++bb) {
            float4 v[8];
            #pragma unroll
            for (int i = 0; i < 8; ++i)
                v[i] = __ldcs(&base[(size_t)(w + (bb * 8 + i) * 4) * 32]);
            #pragma unroll
            for (int i = 0; i < 8; ++i) {
                acc.x += v[i].x; acc.y += v[i].y;
                acc.z += v[i].z; acc.w += v[i].w;
            }
        }
    } else {
        int r = w;
        for (; r + 12 < len; r += 16) {
            float4 v0 = __ldcs(&base[(size_t)(r     ) * 32]);
            float4 v1 = __ldcs(&base[(size_t)(r +  4) * 32]);
            float4 v2 = __ldcs(&base[(size_t)(r +  8) * 32]);
            float4 v3 = __ldcs(&base[(size_t)(r + 12) * 32]);
            acc.x += v0.x + v1.x + v2.x + v3.x;
            acc.y += v0.y + v1.y + v2.y + v3.y;
            acc.z += v0.z + v1.z + v2.z + v3.z;
            acc.w += v0.w + v1.w + v2.w + v3.w;
        }
        for (; r < len; r += 4) {
            float4 v = __ldcs(&base[(size_t)r * 32]);
            acc.x += v.x; acc.y += v.y; acc.z += v.z; acc.w += v.w;
        }
    }

    __shared__ float4 sm[4][32];
    sm[w][l] = acc;
    __syncthreads();

    if (w == 0) {
        float4 a = sm[0][l];
        float4 bb = sm[1][l];
        float4 c = sm[2][l];
        float4 d = sm[3][l];
        const float inv = (len > 0) ? (1.0f / (float)len) : 0.0f;
        float4 o;
        o.x = (a.x + bb.x + c.x + d.x) * inv;
        o.y = (a.y + bb.y + c.y + d.y) * inv;
        o.z = (a.z + bb.z + c.z + d.z) * inv;
        o.w = (a.w + bb.w + c.w + d.w) * inv;
        __stcs(&reinterpret_cast<float4*>(out)[(size_t)seg * 32 + l], o);
    }
}

// ---------------------------------------------------------------------------
// kernel_launch: 2 nodes, PDL-chained (R7-proven structure).
// ---------------------------------------------------------------------------
extern "C" void kernel_launch(void* const* d_in, const int* in_sizes, int n_in,
                              void* d_out, int out_size) {
    const float* data = (const float*)d_in[0];
    const int*   sz   = (const int*)d_in[1];
    float*       out  = (float*)d_out;
    const int n_seg = in_sizes[1];
    const int nb    = (n_seg + SCAN_BLK - 1) / SCAN_BLK;

    scan_local_kernel<<<nb, SCAN_BLK>>>(sz, n_seg);

    cudaLaunchConfig_t cfg = {};
    cfg.gridDim  = dim3((unsigned)n_seg, 1, 1);
    cfg.blockDim = dim3(128, 1, 1);
    cfg.stream = 0;

    cudaLaunchAttribute attrs[1];
    attrs[0].id = cudaLaunchAttributeProgrammaticStreamSerialization;
    attrs[0].val.programmaticStreamSerializationAllowed = 1;
    cfg.attrs = attrs;
    cfg.numAttrs = 1;

    cudaLaunchKernelEx(&cfg, seg_mean_kernel, data, sz, out);
}

// round 14
// speedup vs baseline: 1.0061x; 1.0023x over previous
#include <cuda_runtime.h>
#include <cstdint>

#define MAX_SEGS 65536
#define MAX_NB   64
#define SCAN_BLK 1024

__device__ int g_starts[MAX_SEGS];   // chunk-local exclusive prefix
__device__ int g_blocktot[MAX_NB];   // per-chunk totals

// ---------------------------------------------------------------------------
// K1: per-chunk exclusive scan. grid = ceil(n/1024), block = 1024.
// Deliberately dumb: no atomics, no fences — minimal tail before
// launch_dependents so the dependent grid releases ASAP (R7-proven).
// ---------------------------------------------------------------------------
__global__ void scan_local_kernel(const int* __restrict__ sz, int n) {
    __shared__ int s_tot[32];
    __shared__ int s_off[32];

    const int t    = threadIdx.x;
    const int lane = t & 31;
    const int wid  = t >> 5;
    const int gidx = blockIdx.x * SCAN_BLK + t;

    int v = (gidx < n) ? sz[gidx] : 0;

    int inc = v;
    #pragma unroll
    for (int d = 1; d < 32; d <<= 1) {
        int u = __shfl_up_sync(0xFFFFFFFFu, inc, d);
        if (lane >= d) inc += u;
    }
    if (lane == 31) s_tot[wid] = inc;
    __syncthreads();

    if (wid == 0) {
        int wv = s_tot[lane];
        int winc = wv;
        #pragma unroll
        for (int d = 1; d < 32; d <<= 1) {
            int u = __shfl_up_sync(0xFFFFFFFFu, winc, d);
            if (lane >= d) winc += u;
        }
        s_off[lane] = winc - wv;
        if (lane == 31) g_blocktot[blockIdx.x] = winc;
    }
    __syncthreads();

    if (gidx < n) g_starts[gidx] = s_off[wid] + (inc - v);

    asm volatile("griddepcontrol.launch_dependents;" ::: "memory");
}

// ---------------------------------------------------------------------------
// K2: one CTA per segment. Barrier-free prologue: every warp redundantly
// reduces the predecessor chunk totals (predicated loads + 5 shfl_xor) and
// adds the broadcast g_starts[seg] load. Then the proven MLP=8 body.
// ---------------------------------------------------------------------------
__global__ __launch_bounds__(128)
void seg_mean_kernel(const float* __restrict__ data,
                     const int* __restrict__ sz,
                     float* __restrict__ out) {
    const int seg = blockIdx.x;
    const int t = threadIdx.x;
    const int w = t >> 5;
    const int l = t & 31;

    const int len = sz[seg];            // independent of scan: issue early

    asm volatile("griddepcontrol.wait;" ::: "memory");

    // per-warp redundant reduce of blocktots for chunks < b  (b <= 63)
    const int b = seg >> 10;
    int s = ((l      < b) ? g_blocktot[l]      : 0)
          + ((l + 32 < b) ? g_blocktot[l + 32] : 0);
    #pragma unroll
    for (int d = 16; d > 0; d >>= 1)
        s += __shfl_xor_sync(0xFFFFFFFFu, s, d);
    const int start = s + g_starts[seg];   // broadcast load, same addr all lanes

    const float4* __restrict__ base =
        reinterpret_cast<const float4*>(data) + (size_t)start * 32 + l;

    float4 acc = make_float4(0.f, 0.f, 0.f, 0.f);

    if (len == 64) {
        #pragma unroll
        for (int bb = 0; bb < 2; ++bb) {
            float4 v[8];
            #pragma unroll
            for (int i = 0; i < 8; ++i)
                v[i] = __ldcs(&base[(size_t)(w + (bb * 8 + i) * 4) * 32]);
            #pragma unroll
            for (int i = 0; i < 8; ++i) {
                acc.x += v[i].x; acc.y += v[i].y;
                acc.z += v[i].z; acc.w += v[i].w;
            }
        }
    } else {
        int r = w;
        for (; r + 12 < len; r += 16) {
            float4 v0 = __ldcs(&base[(size_t)(r     ) * 32]);
            float4 v1 = __ldcs(&base[(size_t)(r +  4) * 32]);
            float4 v2 = __ldcs(&base[(size_t)(r +  8) * 32]);
            float4 v3 = __ldcs(&base[(size_t)(r + 12) * 32]);
            acc.x += v0.x + v1.x + v2.x + v3.x;
            acc.y += v0.y + v1.y + v2.y + v3.y;
            acc.z += v0.z + v1.z + v2.z + v3.z;
            acc.w += v0.w + v1.w + v2.w + v3.w;
        }
        for (; r < len; r += 4) {
            float4 v = __ldcs(&base[(size_t)r * 32]);
            acc.x += v.x; acc.y += v.y; acc.z += v.z; acc.w += v.w;
        }
    }

    __shared__ float4 sm[4][32];
    sm[w][l] = acc;
    __syncthreads();

    if (w == 0) {
        float4 a = sm[0][l];
        float4 bb = sm[1][l];
        float4 c = sm[2][l];
        float4 d = sm[3][l];
        const float inv = (len > 0) ? (1.0f / (float)len) : 0.0f;
        float4 o;
        o.x = (a.x + bb.x + c.x + d.x) * inv;
        o.y = (a.y + bb.y + c.y + d.y) * inv;
        o.z = (a.z + bb.z + c.z + d.z) * inv;
        o.w = (a.w + bb.w + c.w + d.w) * inv;
        __stcs(&reinterpret_cast<float4*>(out)[(size_t)seg * 32 + l], o);
    }
}

// ---------------------------------------------------------------------------
// kernel_launch: 2 nodes, PDL-chained (R7-proven structure).
// ---------------------------------------------------------------------------
extern "C" void kernel_launch(void* const* d_in, const int* in_sizes, int n_in,
                              void* d_out, int out_size) {
    const float* data = (const float*)d_in[0];
    const int*   sz   = (const int*)d_in[1];
    float*       out  = (float*)d_out;
    const int n_seg = in_sizes[1];
    const int nb    = (n_seg + SCAN_BLK - 1) / SCAN_BLK;

    scan_local_kernel<<<nb, SCAN_BLK>>>(sz, n_seg);

    cudaLaunchConfig_t cfg = {};
    cfg.gridDim  = dim3((unsigned)n_seg, 1, 1);
    cfg.blockDim = dim3(128, 1, 1);
    cfg.stream = 0;

    cudaLaunchAttribute attrs[1];
    attrs[0].id = cudaLaunchAttributeProgrammaticStreamSerialization;
    attrs[0].val.programmaticStreamSerializationAllowed = 1;
    cfg.attrs = attrs;
    cfg.numAttrs = 1;

    cudaLaunchKernelEx(&cfg, seg_mean_kernel, data, sz, out);
}